// round 1
// baseline (speedup 1.0000x reference)
#include <cuda_runtime.h>
#include <cuda_bf16.h>
#include <math.h>

// ---------------- problem constants ----------------
#define BATCH 16
#define SEQ   1000
#define EMB   512
#define NH    8
#define DH    64
#define FF    2048
#define CBN   4096
#define NL    4
#define E3    1536
#define MTOK  (BATCH*SEQ)       // 16000

// ---------------- scratch (static device globals; no allocation) ----------------
__device__ __align__(16) static float g_x   [MTOK*EMB];
__device__ __align__(16) static float g_y   [MTOK*EMB];
__device__ __align__(16) static float g_h   [MTOK*EMB];
__device__ __align__(16) static float g_qkv [MTOK*E3];
__device__ __align__(16) static float g_ctx [MTOK*EMB];
__device__ __align__(16) static float g_t   [MTOK*FF];
__device__ __align__(16) static float g_enh [MTOK*EMB];
__device__ __align__(16) static float g_cbn2[CBN];
__device__ __align__(16) static float g_pmin[MTOK*32];
__device__ __align__(16) static int   g_pidx[MTOK*32];

// ---------------- embed: x = codebook[tok] + pos_enc ----------------
__global__ void embed_kernel(const int* __restrict__ tok, const float* __restrict__ cb,
                             const float* __restrict__ pe, float* __restrict__ x,
                             float* __restrict__ y)
{
    int i = blockIdx.x * blockDim.x + threadIdx.x;     // float4 index
    if (i >= MTOK * (EMB/4)) return;
    int row = i >> 7;            // token row (EMB/4 = 128 vec per row)
    int c4  = i & 127;
    int s   = row % SEQ;
    int tk  = tok[row];
    float4 a = *(const float4*)(cb + (size_t)tk * EMB + c4*4);
    float4 p = *(const float4*)(pe + (size_t)s  * EMB + c4*4);
    float4 v = make_float4(a.x+p.x, a.y+p.y, a.z+p.z, a.w+p.w);
    ((float4*)x)[i] = v;
    ((float4*)y)[i] = v;
}

// ---------------- layernorm (E=512), optional exact-GELU epilogue ----------------
__global__ void __launch_bounds__(128) ln_kernel(const float* __restrict__ in,
                                                 const float* __restrict__ gam,
                                                 const float* __restrict__ bet,
                                                 float* __restrict__ out, int dogelu)
{
    int row = blockIdx.x;
    int t   = threadIdx.x;
    const float4 v = ((const float4*)(in + (size_t)row * EMB))[t];
    float s  = v.x + v.y + v.z + v.w;
    float ss = v.x*v.x + v.y*v.y + v.z*v.z + v.w*v.w;
    #pragma unroll
    for (int off = 16; off; off >>= 1) {
        s  += __shfl_xor_sync(0xffffffffu, s,  off);
        ss += __shfl_xor_sync(0xffffffffu, ss, off);
    }
    __shared__ float sh[8];
    if ((t & 31) == 0) { sh[t >> 5] = s; sh[4 + (t >> 5)] = ss; }
    __syncthreads();
    s  = sh[0] + sh[1] + sh[2] + sh[3];
    ss = sh[4] + sh[5] + sh[6] + sh[7];
    float mean = s * (1.f / EMB);
    float var  = ss * (1.f / EMB) - mean * mean;
    float rstd = rsqrtf(var + 1e-5f);
    float4 gv = ((const float4*)gam)[t];
    float4 bv = ((const float4*)bet)[t];
    float4 ov;
    ov.x = (v.x - mean) * rstd * gv.x + bv.x;
    ov.y = (v.y - mean) * rstd * gv.y + bv.y;
    ov.z = (v.z - mean) * rstd * gv.z + bv.z;
    ov.w = (v.w - mean) * rstd * gv.w + bv.w;
    if (dogelu) {
        ov.x *= normcdff(ov.x);
        ov.y *= normcdff(ov.y);
        ov.z *= normcdff(ov.z);
        ov.w *= normcdff(ov.w);
    }
    ((float4*)(out + (size_t)row * EMB))[t] = ov;
}

// ---------------- generic GEMM: C[M,N] = A[M,K] @ W[N,K]^T + bias, fused epilogues --------
// MODE: 0 plain, 1 GELU, 2 +resid, 3 resid + scale*(..), 4 argmin (quantize)
#define GBM 128
#define GBN 128
#define GBK 16
#define GPAD 132

template<int MODE>
__global__ void __launch_bounds__(256) gemm_kernel(
    const float* __restrict__ A, const float* __restrict__ W,
    const float* __restrict__ bias, float* __restrict__ C,
    int M, int N, int K,
    const float* __restrict__ resid, const float* __restrict__ scp,
    const float* __restrict__ cbn2, float* __restrict__ pmin, int* __restrict__ pidx)
{
    __shared__ float As[GBK][GPAD];
    __shared__ float Bs[GBK][GPAD];
    const int t    = threadIdx.x;
    const int tidy = t >> 4;      // 0..15 -> row group
    const int tidx = t & 15;      // 0..15 -> col group
    const int m0 = blockIdx.y * GBM;
    const int n0 = blockIdx.x * GBN;
    const float* Ab = A + (size_t)m0 * K;
    const float* Wb = W + (size_t)n0 * K;

    float acc[8][8];
    #pragma unroll
    for (int i = 0; i < 8; i++)
        #pragma unroll
        for (int j = 0; j < 8; j++) acc[i][j] = 0.f;

    for (int k0 = 0; k0 < K; k0 += GBK) {
        #pragma unroll
        for (int i = 0; i < 8; i++) {
            int l = i * 256 + t;
            int r = l >> 4, c = l & 15;
            As[c][r] = Ab[(size_t)r * K + (k0 + c)];
            Bs[c][r] = Wb[(size_t)r * K + (k0 + c)];
        }
        __syncthreads();
        #pragma unroll
        for (int kk = 0; kk < GBK; kk++) {
            float a[8], bb[8];
            *(float4*)&a[0]  = *(const float4*)&As[kk][tidy*8];
            *(float4*)&a[4]  = *(const float4*)&As[kk][tidy*8 + 4];
            *(float4*)&bb[0] = *(const float4*)&Bs[kk][tidx*8];
            *(float4*)&bb[4] = *(const float4*)&Bs[kk][tidx*8 + 4];
            #pragma unroll
            for (int i = 0; i < 8; i++)
                #pragma unroll
                for (int j = 0; j < 8; j++)
                    acc[i][j] = fmaf(a[i], bb[j], acc[i][j]);
        }
        __syncthreads();
    }

    if (MODE == 4) {
        float cb2[8];
        #pragma unroll
        for (int j = 0; j < 8; j++) cb2[j] = cbn2[n0 + tidx*8 + j];
        #pragma unroll
        for (int i = 0; i < 8; i++) {
            int row = m0 + tidy*8 + i;
            float best = 3.4e38f; int bi = 0x7fffffff;
            #pragma unroll
            for (int j = 0; j < 8; j++) {
                float d = fmaf(-2.f, acc[i][j], cb2[j]);
                int n = n0 + tidx*8 + j;
                if (d < best || (d == best && n < bi)) { best = d; bi = n; }
            }
            #pragma unroll
            for (int off = 8; off; off >>= 1) {
                float ov = __shfl_xor_sync(0xffffffffu, best, off);
                int   oi = __shfl_xor_sync(0xffffffffu, bi,   off);
                if (ov < best || (ov == best && oi < bi)) { best = ov; bi = oi; }
            }
            if (tidx == 0) {
                pmin[(size_t)row * gridDim.x + blockIdx.x] = best;
                pidx[(size_t)row * gridDim.x + blockIdx.x] = bi;
            }
        }
        return;
    }

    float scv = 1.f;
    if (MODE == 3) scv = *scp;
    float bv[8];
    #pragma unroll
    for (int j = 0; j < 8; j++) bv[j] = bias[n0 + tidx*8 + j];
    #pragma unroll
    for (int i = 0; i < 8; i++) {
        size_t row = (size_t)(m0 + tidy*8 + i);
        float* Cr = C + row * N + n0 + tidx*8;
        const float* Rr = (MODE == 2 || MODE == 3) ? (resid + row * N + n0 + tidx*8) : C;
        float outv[8];
        #pragma unroll
        for (int j = 0; j < 8; j++) {
            float c = acc[i][j] + bv[j];
            if (MODE == 1) c = c * normcdff(c);
            if (MODE == 2) c = c + Rr[j];
            if (MODE == 3) c = Rr[j] + scv * c;
            outv[j] = c;
        }
        *(float4*)&Cr[0] = *(float4*)&outv[0];
        *(float4*)&Cr[4] = *(float4*)&outv[4];
    }
}

// ---------------- flash attention: one block per (b, h, 64-q tile) ----------------
#define APAD 68
#define ASMEM (3 * 64 * APAD * 4)

__global__ void __launch_bounds__(128) attn_kernel(const float* __restrict__ qkv,
                                                   float* __restrict__ ctx)
{
    extern __shared__ float sm[];
    float* Qs = sm;                  // Qs[d][q]  (transposed, pre-scaled)
    float* KP = sm + 64 * APAD;      // K[d][kk] during scores, then P[kk][q]
    float* Vs = sm + 2 * 64 * APAD;  // V[kk][dd]
    const int t    = threadIdx.x;
    const int tidy = t >> 4;         // 0..7  -> q-row group of 8
    const int tidx = t & 15;         // 0..15 -> col group of 4
    const int q0 = blockIdx.x * 64;
    const int h  = blockIdx.y;
    const int b  = blockIdx.z;
    const float* base = qkv + (size_t)b * SEQ * E3 + h * DH;

    // load Q (transposed + scaled by 1/sqrt(DH))
    #pragma unroll
    for (int i = 0; i < 8; i++) {
        int l = i * 128 + t;
        int r = l >> 4, c4 = l & 15;
        float4 v = make_float4(0.f, 0.f, 0.f, 0.f);
        if (q0 + r < SEQ)
            v = *(const float4*)(base + (size_t)(q0 + r) * E3 + c4 * 4);
        const float sc = 0.125f;
        Qs[(c4*4+0)*APAD + r] = v.x * sc;
        Qs[(c4*4+1)*APAD + r] = v.y * sc;
        Qs[(c4*4+2)*APAD + r] = v.z * sc;
        Qs[(c4*4+3)*APAD + r] = v.w * sc;
    }

    float o[8][4], mrow[8], lrow[8];
    #pragma unroll
    for (int i = 0; i < 8; i++) {
        mrow[i] = -1e30f; lrow[i] = 0.f;
        #pragma unroll
        for (int j = 0; j < 4; j++) o[i][j] = 0.f;
    }

    for (int kt = 0; kt < (SEQ + 63) / 64; kt++) {
        int k0 = kt * 64;
        __syncthreads();  // Q visible (first iter) / previous PV finished
        #pragma unroll
        for (int i = 0; i < 8; i++) {
            int l = i * 128 + t;
            int r = l >> 4, c4 = l & 15;
            float4 kv = make_float4(0.f,0.f,0.f,0.f);
            float4 vv = make_float4(0.f,0.f,0.f,0.f);
            if (k0 + r < SEQ) {
                kv = *(const float4*)(base + (size_t)(k0 + r) * E3 + EMB   + c4 * 4);
                vv = *(const float4*)(base + (size_t)(k0 + r) * E3 + 2*EMB + c4 * 4);
            }
            KP[(c4*4+0)*APAD + r] = kv.x;
            KP[(c4*4+1)*APAD + r] = kv.y;
            KP[(c4*4+2)*APAD + r] = kv.z;
            KP[(c4*4+3)*APAD + r] = kv.w;
            *(float4*)(Vs + r * APAD + c4 * 4) = vv;
        }
        __syncthreads();

        float s[8][4];
        #pragma unroll
        for (int i = 0; i < 8; i++)
            #pragma unroll
            for (int j = 0; j < 4; j++) s[i][j] = 0.f;
        #pragma unroll
        for (int d = 0; d < 64; d++) {
            float a[8], bb[4];
            *(float4*)&a[0]  = *(const float4*)(Qs + d * APAD + tidy*8);
            *(float4*)&a[4]  = *(const float4*)(Qs + d * APAD + tidy*8 + 4);
            *(float4*)&bb[0] = *(const float4*)(KP + d * APAD + tidx*4);
            #pragma unroll
            for (int i = 0; i < 8; i++)
                #pragma unroll
                for (int j = 0; j < 4; j++)
                    s[i][j] = fmaf(a[i], bb[j], s[i][j]);
        }
        if (k0 + 64 > SEQ) {
            #pragma unroll
            for (int j = 0; j < 4; j++)
                if (k0 + tidx*4 + j >= SEQ) {
                    #pragma unroll
                    for (int i = 0; i < 8; i++) s[i][j] = -1e30f;
                }
        }
        // online softmax update
        #pragma unroll
        for (int i = 0; i < 8; i++) {
            float mx = fmaxf(fmaxf(s[i][0], s[i][1]), fmaxf(s[i][2], s[i][3]));
            #pragma unroll
            for (int off = 8; off; off >>= 1)
                mx = fmaxf(mx, __shfl_xor_sync(0xffffffffu, mx, off));
            float mn = fmaxf(mrow[i], mx);
            float alpha = __expf(mrow[i] - mn);
            mrow[i] = mn;
            float rs = 0.f;
            #pragma unroll
            for (int j = 0; j < 4; j++) {
                float p = __expf(s[i][j] - mn);
                s[i][j] = p; rs += p;
            }
            #pragma unroll
            for (int off = 8; off; off >>= 1)
                rs += __shfl_xor_sync(0xffffffffu, rs, off);
            lrow[i] = lrow[i] * alpha + rs;
            #pragma unroll
            for (int j = 0; j < 4; j++) o[i][j] *= alpha;
        }
        __syncthreads();  // done reading KP as K
        #pragma unroll
        for (int i = 0; i < 8; i++)
            #pragma unroll
            for (int j = 0; j < 4; j++)
                KP[(tidx*4 + j) * APAD + tidy*8 + i] = s[i][j];
        __syncthreads();
        // O += P @ V
        #pragma unroll
        for (int kk = 0; kk < 64; kk++) {
            float a[8], bb[4];
            *(float4*)&a[0]  = *(const float4*)(KP + kk * APAD + tidy*8);
            *(float4*)&a[4]  = *(const float4*)(KP + kk * APAD + tidy*8 + 4);
            *(float4*)&bb[0] = *(const float4*)(Vs + kk * APAD + tidx*4);
            #pragma unroll
            for (int i = 0; i < 8; i++)
                #pragma unroll
                for (int j = 0; j < 4; j++)
                    o[i][j] = fmaf(a[i], bb[j], o[i][j]);
        }
    }

    #pragma unroll
    for (int i = 0; i < 8; i++) {
        int q = q0 + tidy*8 + i;
        if (q < SEQ) {
            float inv = 1.f / lrow[i];
            float4 w = make_float4(o[i][0]*inv, o[i][1]*inv, o[i][2]*inv, o[i][3]*inv);
            *(float4*)(ctx + (size_t)(b * SEQ + q) * EMB + h * DH + tidx*4) = w;
        }
    }
}

// ---------------- codebook squared norms ----------------
__global__ void sqnorm_kernel(const float* __restrict__ cb, float* __restrict__ out)
{
    int gid  = blockIdx.x * blockDim.x + threadIdx.x;
    int row  = gid >> 5, lane = gid & 31;
    if (row >= CBN) return;
    const float* r = cb + (size_t)row * EMB;
    float s = 0.f;
    for (int c = lane; c < EMB; c += 32) { float v = r[c]; s = fmaf(v, v, s); }
    #pragma unroll
    for (int off = 16; off; off >>= 1) s += __shfl_xor_sync(0xffffffffu, s, off);
    if (lane == 0) out[row] = s;
}

// ---------------- final argmin reduce over 32 column-block partials ----------------
__global__ void argmin_reduce(const float* __restrict__ pmin, const int* __restrict__ pidx,
                              float* __restrict__ outTok)
{
    int gid  = blockIdx.x * blockDim.x + threadIdx.x;
    int row  = gid >> 5, lane = gid & 31;
    if (row >= MTOK) return;
    float v = pmin[row * 32 + lane];
    int  id = pidx[row * 32 + lane];
    #pragma unroll
    for (int off = 16; off; off >>= 1) {
        float ov = __shfl_xor_sync(0xffffffffu, v,  off);
        int   oi = __shfl_xor_sync(0xffffffffu, id, off);
        if (ov < v || (ov == v && oi < id)) { v = ov; id = oi; }
    }
    if (lane == 0) outTok[row] = (float)id;
}

// ---------------- host orchestration ----------------
static inline void run_gemm(int mode, const float* A, const float* W, const float* bias,
                            float* C, int M, int N, int K,
                            const float* resid, const float* sc)
{
    dim3 grid(N / GBN, M / GBM);
    switch (mode) {
    case 0: gemm_kernel<0><<<grid, 256>>>(A, W, bias, C, M, N, K, resid, sc, nullptr, nullptr, nullptr); break;
    case 1: gemm_kernel<1><<<grid, 256>>>(A, W, bias, C, M, N, K, resid, sc, nullptr, nullptr, nullptr); break;
    case 2: gemm_kernel<2><<<grid, 256>>>(A, W, bias, C, M, N, K, resid, sc, nullptr, nullptr, nullptr); break;
    case 3: gemm_kernel<3><<<grid, 256>>>(A, W, bias, C, M, N, K, resid, sc, nullptr, nullptr, nullptr); break;
    }
}

extern "C" void kernel_launch(void* const* d_in, const int* in_sizes, int n_in,
                              void* d_out, int out_size)
{
    const int*   tok    = (const int*)  d_in[0];
    const float* cb     = (const float*)d_in[1];
    const float* pe     = (const float*)d_in[2];
    const float* qkv_w  = (const float*)d_in[3];
    const float* qkv_b  = (const float*)d_in[4];
    const float* out_w  = (const float*)d_in[5];
    const float* out_b  = (const float*)d_in[6];
    const float* ln1_g  = (const float*)d_in[7];
    const float* ln1_b  = (const float*)d_in[8];
    const float* ln2_g  = (const float*)d_in[9];
    const float* ln2_b  = (const float*)d_in[10];
    const float* ff1_w  = (const float*)d_in[11];
    const float* ff1_b  = (const float*)d_in[12];
    const float* ff2_w  = (const float*)d_in[13];
    const float* ff2_b  = (const float*)d_in[14];
    const float* fin_g  = (const float*)d_in[15];
    const float* fin_b  = (const float*)d_in[16];
    const float* pp1_w  = (const float*)d_in[17];
    const float* pp1_b  = (const float*)d_in[18];
    const float* ppln_g = (const float*)d_in[19];
    const float* ppln_b = (const float*)d_in[20];
    const float* pp2_w  = (const float*)d_in[21];
    const float* pp2_b  = (const float*)d_in[22];
    const float* res_w  = (const float*)d_in[23];
    const float* fc1_w  = (const float*)d_in[24];
    const float* fc1_b  = (const float*)d_in[25];
    const float* fcln_g = (const float*)d_in[26];
    const float* fcln_b = (const float*)d_in[27];
    const float* fc2_w  = (const float*)d_in[28];
    const float* fc2_b  = (const float*)d_in[29];

    float *x, *y, *h, *qkv, *ctx, *tbuf, *enh, *cbn2, *pmin; int* pidx;
    cudaGetSymbolAddress((void**)&x,    g_x);
    cudaGetSymbolAddress((void**)&y,    g_y);
    cudaGetSymbolAddress((void**)&h,    g_h);
    cudaGetSymbolAddress((void**)&qkv,  g_qkv);
    cudaGetSymbolAddress((void**)&ctx,  g_ctx);
    cudaGetSymbolAddress((void**)&tbuf, g_t);
    cudaGetSymbolAddress((void**)&enh,  g_enh);
    cudaGetSymbolAddress((void**)&cbn2, g_cbn2);
    cudaGetSymbolAddress((void**)&pmin, g_pmin);
    cudaGetSymbolAddress((void**)&pidx, g_pidx);

    cudaFuncSetAttribute(attn_kernel, cudaFuncAttributeMaxDynamicSharedMemorySize, ASMEM);

    float* fc_out = (float*)d_out;
    const int M = MTOK;

    embed_kernel<<<(M * (EMB/4) + 255) / 256, 256>>>(tok, cb, pe, x, y);

    for (int l = 0; l < NL; l++) {
        ln_kernel<<<M, 128>>>(y, ln1_g + l*EMB, ln1_b + l*EMB, h, 0);
        run_gemm(0, h, qkv_w + (size_t)l*E3*EMB, qkv_b + (size_t)l*E3, qkv, M, E3, EMB, nullptr, nullptr);
        attn_kernel<<<dim3((SEQ+63)/64, NH, BATCH), 128, ASMEM>>>(qkv, ctx);
        run_gemm(2, ctx, out_w + (size_t)l*EMB*EMB, out_b + (size_t)l*EMB, y, M, EMB, EMB, y, nullptr);
        ln_kernel<<<M, 128>>>(y, ln2_g + l*EMB, ln2_b + l*EMB, h, 0);
        run_gemm(1, h, ff1_w + (size_t)l*FF*EMB, ff1_b + (size_t)l*FF, tbuf, M, FF, EMB, nullptr, nullptr);
        run_gemm(2, tbuf, ff2_w + (size_t)l*EMB*FF, ff2_b + (size_t)l*EMB, y, M, EMB, FF, y, nullptr);
    }

    ln_kernel<<<M, 128>>>(y, fin_g, fin_b, h, 0);
    run_gemm(0, h, pp1_w, pp1_b, ctx, M, EMB, EMB, nullptr, nullptr);
    ln_kernel<<<M, 128>>>(ctx, ppln_g, ppln_b, tbuf, 1);
    run_gemm(3, tbuf, pp2_w, pp2_b, enh, M, EMB, EMB, x, res_w);
    run_gemm(0, enh, fc1_w, fc1_b, ctx, M, EMB, EMB, nullptr, nullptr);
    ln_kernel<<<M, 128>>>(ctx, fcln_g, fcln_b, tbuf, 1);
    run_gemm(0, tbuf, fc2_w, fc2_b, fc_out, M, EMB, EMB, nullptr, nullptr);

    if (out_size >= MTOK * EMB + MTOK) {
        sqnorm_kernel<<<(CBN * 32 + 255) / 256, 256>>>(cb, cbn2);
        dim3 grid(CBN / GBN, M / GBM);
        gemm_kernel<4><<<grid, 256>>>(fc_out, cb, nullptr, nullptr, M, CBN, EMB,
                                      nullptr, nullptr, cbn2, pmin, pidx);
        argmin_reduce<<<(MTOK * 32 + 255) / 256, 256>>>(pmin, pidx, fc_out + (size_t)MTOK * EMB);
    }
}

// round 4
// speedup vs baseline: 2.0869x; 2.0869x over previous
#include <cuda_runtime.h>
#include <cuda_bf16.h>
#include <math.h>
#include <stdint.h>

// ---------------- problem constants ----------------
#define BATCH 16
#define SEQ   1000
#define EMB   512
#define NH    8
#define DH    64
#define FF    2048
#define CBN   4096
#define NL    4
#define E3    1536
#define MTOK  (BATCH*SEQ)       // 16000
#define NCAND 64                // quantize candidates per row (2 per 128-col block)

// ---------------- scratch (static device globals; no allocation) ----------------
__device__ __align__(16) static float g_x   [MTOK*EMB];
__device__ __align__(16) static float g_y   [MTOK*EMB];
__device__ __align__(16) static float g_h   [MTOK*EMB];
__device__ __align__(16) static float g_qkv [MTOK*E3];
__device__ __align__(16) static float g_ctx [MTOK*EMB];
__device__ __align__(16) static float g_t   [MTOK*FF];
__device__ __align__(16) static float g_enh [MTOK*EMB];
__device__ __align__(16) static float g_cbn2[CBN];
__device__ __align__(16) static int   g_pidx[MTOK*NCAND];

// ================= helpers =================
__device__ __forceinline__ uint32_t smem_u32(const void* p) {
    uint32_t a;
    asm("{ .reg .u64 t; cvta.to.shared.u64 t, %1; cvt.u32.u64 %0, t; }" : "=r"(a) : "l"(p));
    return a;
}

__device__ __forceinline__ void ldsm4(uint32_t* r, uint32_t addr) {
    asm volatile("ldmatrix.sync.aligned.m8n8.x4.shared.b16 {%0,%1,%2,%3}, [%4];"
                 : "=r"(r[0]), "=r"(r[1]), "=r"(r[2]), "=r"(r[3]) : "r"(addr));
}

__device__ __forceinline__ void mma_bf16(float* c, const uint32_t* a, const uint32_t* b) {
    asm volatile("mma.sync.aligned.m16n8k16.row.col.f32.bf16.bf16.f32 "
                 "{%0,%1,%2,%3}, {%4,%5,%6,%7}, {%8,%9}, {%0,%1,%2,%3};"
                 : "+f"(c[0]), "+f"(c[1]), "+f"(c[2]), "+f"(c[3])
                 : "r"(a[0]), "r"(a[1]), "r"(a[2]), "r"(a[3]), "r"(b[0]), "r"(b[1]));
}

__device__ __forceinline__ uint32_t sw128(uint32_t off) {
    return off ^ ((off >> 3) & 0x70);
}

// fp32x4 -> hi/lo bf16x2 pairs
__device__ __forceinline__ void cvt_hilo(float4 v, uint2& hi, uint2& lo) {
    uint32_t h0, h1;
    asm("cvt.rn.bf16x2.f32 %0, %1, %2;" : "=r"(h0) : "f"(v.y), "f"(v.x));
    asm("cvt.rn.bf16x2.f32 %0, %1, %2;" : "=r"(h1) : "f"(v.w), "f"(v.z));
    float hx = __uint_as_float(h0 << 16);
    float hy = __uint_as_float(h0 & 0xffff0000u);
    float hz = __uint_as_float(h1 << 16);
    float hw = __uint_as_float(h1 & 0xffff0000u);
    uint32_t l0, l1;
    asm("cvt.rn.bf16x2.f32 %0, %1, %2;" : "=r"(l0) : "f"(v.y - hy), "f"(v.x - hx));
    asm("cvt.rn.bf16x2.f32 %0, %1, %2;" : "=r"(l1) : "f"(v.w - hw), "f"(v.z - hz));
    hi = make_uint2(h0, h1);
    lo = make_uint2(l0, l1);
}

// store one float4 (4 k-elems) as hi/lo into a 128B-row tile; row layout [hi 64B | lo 64B]
__device__ __forceinline__ void sts_hilo(char* tile, int row, int c4, float4 v) {
    uint2 hi, lo;
    cvt_hilo(v, hi, lo);
    uint32_t off = (uint32_t)(row * 128 + c4 * 8);
    *(uint2*)(tile + sw128(off))      = hi;
    *(uint2*)(tile + sw128(off + 64)) = lo;
}

// ---------------- embed ----------------
__global__ void embed_kernel(const int* __restrict__ tok, const float* __restrict__ cb,
                             const float* __restrict__ pe, float* __restrict__ x,
                             float* __restrict__ y)
{
    int i = blockIdx.x * blockDim.x + threadIdx.x;
    if (i >= MTOK * (EMB/4)) return;
    int row = i >> 7;
    int c4  = i & 127;
    int s   = row % SEQ;
    int tk  = tok[row];
    float4 a = *(const float4*)(cb + (size_t)tk * EMB + c4*4);
    float4 p = *(const float4*)(pe + (size_t)s  * EMB + c4*4);
    float4 v = make_float4(a.x+p.x, a.y+p.y, a.z+p.z, a.w+p.w);
    ((float4*)x)[i] = v;
    ((float4*)y)[i] = v;
}

// ---------------- layernorm ----------------
__global__ void __launch_bounds__(128) ln_kernel(const float* __restrict__ in,
                                                 const float* __restrict__ gam,
                                                 const float* __restrict__ bet,
                                                 float* __restrict__ out, int dogelu)
{
    int row = blockIdx.x;
    int t   = threadIdx.x;
    const float4 v = ((const float4*)(in + (size_t)row * EMB))[t];
    float s  = v.x + v.y + v.z + v.w;
    float ss = v.x*v.x + v.y*v.y + v.z*v.z + v.w*v.w;
    #pragma unroll
    for (int off = 16; off; off >>= 1) {
        s  += __shfl_xor_sync(0xffffffffu, s,  off);
        ss += __shfl_xor_sync(0xffffffffu, ss, off);
    }
    __shared__ float sh[8];
    if ((t & 31) == 0) { sh[t >> 5] = s; sh[4 + (t >> 5)] = ss; }
    __syncthreads();
    s  = sh[0] + sh[1] + sh[2] + sh[3];
    ss = sh[4] + sh[5] + sh[6] + sh[7];
    float mean = s * (1.f / EMB);
    float var  = ss * (1.f / EMB) - mean * mean;
    float rstd = rsqrtf(var + 1e-5f);
    float4 gv = ((const float4*)gam)[t];
    float4 bv = ((const float4*)bet)[t];
    float4 ov;
    ov.x = (v.x - mean) * rstd * gv.x + bv.x;
    ov.y = (v.y - mean) * rstd * gv.y + bv.y;
    ov.z = (v.z - mean) * rstd * gv.z + bv.z;
    ov.w = (v.w - mean) * rstd * gv.w + bv.w;
    if (dogelu) {
        ov.x *= normcdff(ov.x);
        ov.y *= normcdff(ov.y);
        ov.z *= normcdff(ov.z);
        ov.w *= normcdff(ov.w);
    }
    ((float4*)(out + (size_t)row * EMB))[t] = ov;
}

// ================= mma.sync GEMM =================
// C[M,N] = A[M,K] @ W[N,K]^T, fp32 I/O, bf16 hi/lo split (3 HMMA per op pair).
// CTA tile 128x128, warp grid 2x4 (warp tile 64x32), K-chunk 32, double-buffered.
// MODE: 0 bias, 1 bias+GELU, 2 bias+resid, 3 resid+scale*(.+bias), 4 top-2 candidates
#define STAGE_B 32768           // A tile 16KB + B tile 16KB
#define GEMM_SMEM (2*STAGE_B + 1024)

template<int MODE>
__global__ void __launch_bounds__(256) gemm_mma(
    const float* __restrict__ A, const float* __restrict__ W,
    const float* __restrict__ bias, float* __restrict__ C,
    int M, int N, int K,
    const float* __restrict__ resid, const float* __restrict__ scp,
    const float* __restrict__ cbn2, int* __restrict__ pidx)
{
    extern __shared__ char smraw[];
    uint32_t raw = smem_u32(smraw);
    uint32_t base = (raw + 1023) & ~1023u;
    char* sm0 = smraw + (base - raw);

    const int t    = threadIdx.x;
    const int lane = t & 31;
    const int w    = t >> 5;
    const int wm   = w >> 2;       // 0..1
    const int wn   = w & 3;        // 0..3
    const int m0 = blockIdx.y * 128;
    const int n0 = blockIdx.x * 128;
    const int chunks = K / 32;

    float acc[4][4][4];
    #pragma unroll
    for (int i = 0; i < 4; i++)
        #pragma unroll
        for (int j = 0; j < 4; j++)
            #pragma unroll
            for (int k = 0; k < 4; k++) acc[i][j][k] = 0.f;

    // prologue: stage chunk 0 into buffer 0
    {
        char* dA = sm0;
        char* dB = sm0 + 16384;
        #pragma unroll
        for (int i = 0; i < 4; i++) {
            int idx = i * 256 + t;
            int row = idx >> 3, c4 = idx & 7;
            float4 va = *(const float4*)(A + (size_t)(m0 + row) * K + c4 * 4);
            float4 vb = *(const float4*)(W + (size_t)(n0 + row) * K + c4 * 4);
            sts_hilo(dA, row, c4, va);
            sts_hilo(dB, row, c4, vb);
        }
        __syncthreads();
    }

    // per-lane ldmatrix base byte offsets (pre-swizzle)
    const uint32_t aoff0 = (uint32_t)((wm * 64 + (lane & 15)) * 128 + (lane >> 4) * 16);
    const uint32_t boff0 = (uint32_t)((wn * 32 + ((lane >> 4) << 3) + (lane & 7)) * 128
                                      + ((lane >> 3) & 1) * 16);

    for (int c = 0; c < chunks; c++) {
        int buf = c & 1;
        float4 pa[4], pb[4];
        if (c + 1 < chunks) {
            int k0 = (c + 1) * 32;
            #pragma unroll
            for (int i = 0; i < 4; i++) {
                int idx = i * 256 + t;
                int row = idx >> 3, c4 = idx & 7;
                pa[i] = *(const float4*)(A + (size_t)(m0 + row) * K + k0 + c4 * 4);
                pb[i] = *(const float4*)(W + (size_t)(n0 + row) * K + k0 + c4 * 4);
            }
        }

        uint32_t tA = base + buf * STAGE_B;
        uint32_t tB = tA + 16384;
        #pragma unroll
        for (int ks = 0; ks < 2; ks++) {
            uint32_t ah[4][4], al[4][4], bh[4][2], bl[4][2];
            #pragma unroll
            for (int mt = 0; mt < 4; mt++) {
                uint32_t offh = aoff0 + mt * (16 * 128) + ks * 32;
                ldsm4(ah[mt], tA + sw128(offh));
                ldsm4(al[mt], tA + sw128(offh + 64));
            }
            #pragma unroll
            for (int np = 0; np < 2; np++) {
                uint32_t offh = boff0 + np * (16 * 128) + ks * 32;
                uint32_t r[4];
                ldsm4(r, tB + sw128(offh));
                bh[np*2][0] = r[0]; bh[np*2][1] = r[1];
                bh[np*2+1][0] = r[2]; bh[np*2+1][1] = r[3];
                ldsm4(r, tB + sw128(offh + 64));
                bl[np*2][0] = r[0]; bl[np*2][1] = r[1];
                bl[np*2+1][0] = r[2]; bl[np*2+1][1] = r[3];
            }
            #pragma unroll
            for (int mt = 0; mt < 4; mt++)
                #pragma unroll
                for (int nt = 0; nt < 4; nt++) {
                    mma_bf16(acc[mt][nt], ah[mt], bh[nt]);
                    mma_bf16(acc[mt][nt], ah[mt], bl[nt]);
                    mma_bf16(acc[mt][nt], al[mt], bh[nt]);
                }
        }
        __syncthreads();
        if (c + 1 < chunks) {
            char* dA = sm0 + (buf ^ 1) * STAGE_B;
            char* dB = dA + 16384;
            #pragma unroll
            for (int i = 0; i < 4; i++) {
                int idx = i * 256 + t;
                int row = idx >> 3, c4 = idx & 7;
                sts_hilo(dA, row, c4, pa[i]);
                sts_hilo(dB, row, c4, pb[i]);
            }
            __syncthreads();
        }
    }

    if (MODE == 4) {
        // emit top-2 approximate candidates per row per 128-col block
        float* psm = (float*)sm0;              // [128][4][2] values
        int*   pim = (int*)(sm0 + 128*4*2*4);  // [128][4][2] indices
        #pragma unroll
        for (int mt = 0; mt < 4; mt++) {
            float b0[2] = {3.4e38f, 3.4e38f}, b1[2] = {3.4e38f, 3.4e38f};
            int   i0v[2] = {0x7fffffff, 0x7fffffff}, i1v[2] = {0x7fffffff, 0x7fffffff};
            #pragma unroll
            for (int nt = 0; nt < 4; nt++) {
                int n = n0 + wn * 32 + nt * 8 + (lane & 3) * 2;
                float c0 = cbn2[n], c1 = cbn2[n + 1];
                float dv[2][2];
                dv[0][0] = fmaf(-2.f, acc[mt][nt][0], c0);
                dv[0][1] = fmaf(-2.f, acc[mt][nt][1], c1);
                dv[1][0] = fmaf(-2.f, acc[mt][nt][2], c0);
                dv[1][1] = fmaf(-2.f, acc[mt][nt][3], c1);
                #pragma unroll
                for (int rr = 0; rr < 2; rr++)
                    #pragma unroll
                    for (int jj = 0; jj < 2; jj++) {
                        float d = dv[rr][jj]; int nn = n + jj;
                        if (d < b0[rr] || (d == b0[rr] && nn < i0v[rr])) {
                            b1[rr] = b0[rr]; i1v[rr] = i0v[rr];
                            b0[rr] = d; i0v[rr] = nn;
                        } else if (d < b1[rr] || (d == b1[rr] && nn < i1v[rr])) {
                            b1[rr] = d; i1v[rr] = nn;
                        }
                    }
            }
            #pragma unroll
            for (int off = 1; off < 4; off <<= 1) {
                #pragma unroll
                for (int rr = 0; rr < 2; rr++) {
                    float o0 = __shfl_xor_sync(0xffffffffu, b0[rr], off);
                    int   q0 = __shfl_xor_sync(0xffffffffu, i0v[rr], off);
                    float o1 = __shfl_xor_sync(0xffffffffu, b1[rr], off);
                    int   q1 = __shfl_xor_sync(0xffffffffu, i1v[rr], off);
                    if (o0 < b0[rr] || (o0 == b0[rr] && q0 < i0v[rr])) {
                        b1[rr] = b0[rr]; i1v[rr] = i0v[rr];
                        b0[rr] = o0; i0v[rr] = q0;
                    } else if (o0 < b1[rr] || (o0 == b1[rr] && q0 < i1v[rr])) {
                        b1[rr] = o0; i1v[rr] = q0;
                    }
                    if (o1 < b1[rr] || (o1 == b1[rr] && q1 < i1v[rr])) {
                        b1[rr] = o1; i1v[rr] = q1;
                    }
                }
            }
            if ((lane & 3) == 0) {
                int rl = wm * 64 + mt * 16 + (lane >> 2);
                psm[(rl*4 + wn)*2 + 0]     = b0[0]; pim[(rl*4 + wn)*2 + 0]     = i0v[0];
                psm[(rl*4 + wn)*2 + 1]     = b1[0]; pim[(rl*4 + wn)*2 + 1]     = i1v[0];
                psm[((rl+8)*4 + wn)*2 + 0] = b0[1]; pim[((rl+8)*4 + wn)*2 + 0] = i0v[1];
                psm[((rl+8)*4 + wn)*2 + 1] = b1[1]; pim[((rl+8)*4 + wn)*2 + 1] = i1v[1];
            }
        }
        __syncthreads();
        if (t < 128) {
            float b0 = 3.4e38f, b1 = 3.4e38f;
            int i0 = 0x7fffffff, i1 = 0x7fffffff;
            #pragma unroll
            for (int j = 0; j < 8; j++) {
                float v = psm[t*8 + j]; int id = pim[t*8 + j];
                if (v < b0 || (v == b0 && id < i0)) {
                    b1 = b0; i1 = i0; b0 = v; i0 = id;
                } else if (v < b1 || (v == b1 && id < i1)) {
                    b1 = v; i1 = id;
                }
            }
            size_t o = (size_t)(m0 + t) * NCAND + blockIdx.x * 2;
            pidx[o]     = i0;
            pidx[o + 1] = i1;
        }
        return;
    }

    const float scv = (MODE == 3) ? *scp : 1.f;
    #pragma unroll
    for (int mt = 0; mt < 4; mt++) {
        int rb = m0 + wm * 64 + mt * 16 + (lane >> 2);
        #pragma unroll
        for (int nt = 0; nt < 4; nt++) {
            int col = n0 + wn * 32 + nt * 8 + (lane & 3) * 2;
            float b0 = bias[col], b1 = bias[col + 1];
            float v0 = acc[mt][nt][0] + b0;
            float v1 = acc[mt][nt][1] + b1;
            float v2 = acc[mt][nt][2] + b0;
            float v3 = acc[mt][nt][3] + b1;
            size_t o0 = (size_t)rb * N + col;
            size_t o1 = (size_t)(rb + 8) * N + col;
            if (MODE == 1) {
                v0 *= normcdff(v0); v1 *= normcdff(v1);
                v2 *= normcdff(v2); v3 *= normcdff(v3);
            }
            if (MODE == 2) {
                v0 += resid[o0]; v1 += resid[o0 + 1];
                v2 += resid[o1]; v3 += resid[o1 + 1];
            }
            if (MODE == 3) {
                v0 = resid[o0] + scv * v0; v1 = resid[o0 + 1] + scv * v1;
                v2 = resid[o1] + scv * v2; v3 = resid[o1 + 1] + scv * v3;
            }
            *(float2*)(C + o0) = make_float2(v0, v1);
            *(float2*)(C + o1) = make_float2(v2, v3);
        }
    }
}

// ---------------- flash attention (fp32 SIMT) ----------------
#define APAD 68
#define ASMEM (3 * 64 * APAD * 4)

__global__ void __launch_bounds__(128) attn_kernel(const float* __restrict__ qkv,
                                                   float* __restrict__ ctx)
{
    extern __shared__ float sm[];
    float* Qs = sm;
    float* KP = sm + 64 * APAD;
    float* Vs = sm + 2 * 64 * APAD;
    const int t    = threadIdx.x;
    const int tidy = t >> 4;
    const int tidx = t & 15;
    const int q0 = blockIdx.x * 64;
    const int h  = blockIdx.y;
    const int b  = blockIdx.z;
    const float* base = qkv + (size_t)b * SEQ * E3 + h * DH;

    #pragma unroll
    for (int i = 0; i < 8; i++) {
        int l = i * 128 + t;
        int r = l >> 4, c4 = l & 15;
        float4 v = make_float4(0.f, 0.f, 0.f, 0.f);
        if (q0 + r < SEQ)
            v = *(const float4*)(base + (size_t)(q0 + r) * E3 + c4 * 4);
        const float sc = 0.125f;
        Qs[(c4*4+0)*APAD + r] = v.x * sc;
        Qs[(c4*4+1)*APAD + r] = v.y * sc;
        Qs[(c4*4+2)*APAD + r] = v.z * sc;
        Qs[(c4*4+3)*APAD + r] = v.w * sc;
    }

    float o[8][4], mrow[8], lrow[8];
    #pragma unroll
    for (int i = 0; i < 8; i++) {
        mrow[i] = -1e30f; lrow[i] = 0.f;
        #pragma unroll
        for (int j = 0; j < 4; j++) o[i][j] = 0.f;
    }

    for (int kt = 0; kt < (SEQ + 63) / 64; kt++) {
        int k0 = kt * 64;
        __syncthreads();
        #pragma unroll
        for (int i = 0; i < 8; i++) {
            int l = i * 128 + t;
            int r = l >> 4, c4 = l & 15;
            float4 kv = make_float4(0.f,0.f,0.f,0.f);
            float4 vv = make_float4(0.f,0.f,0.f,0.f);
            if (k0 + r < SEQ) {
                kv = *(const float4*)(base + (size_t)(k0 + r) * E3 + EMB   + c4 * 4);
                vv = *(const float4*)(base + (size_t)(k0 + r) * E3 + 2*EMB + c4 * 4);
            }
            KP[(c4*4+0)*APAD + r] = kv.x;
            KP[(c4*4+1)*APAD + r] = kv.y;
            KP[(c4*4+2)*APAD + r] = kv.z;
            KP[(c4*4+3)*APAD + r] = kv.w;
            *(float4*)(Vs + r * APAD + c4 * 4) = vv;
        }
        __syncthreads();

        float s[8][4];
        #pragma unroll
        for (int i = 0; i < 8; i++)
            #pragma unroll
            for (int j = 0; j < 4; j++) s[i][j] = 0.f;
        #pragma unroll
        for (int d = 0; d < 64; d++) {
            float a[8], bb[4];
            *(float4*)&a[0]  = *(const float4*)(Qs + d * APAD + tidy*8);
            *(float4*)&a[4]  = *(const float4*)(Qs + d * APAD + tidy*8 + 4);
            *(float4*)&bb[0] = *(const float4*)(KP + d * APAD + tidx*4);
            #pragma unroll
            for (int i = 0; i < 8; i++)
                #pragma unroll
                for (int j = 0; j < 4; j++)
                    s[i][j] = fmaf(a[i], bb[j], s[i][j]);
        }
        if (k0 + 64 > SEQ) {
            #pragma unroll
            for (int j = 0; j < 4; j++)
                if (k0 + tidx*4 + j >= SEQ) {
                    #pragma unroll
                    for (int i = 0; i < 8; i++) s[i][j] = -1e30f;
                }
        }
        #pragma unroll
        for (int i = 0; i < 8; i++) {
            float mx = fmaxf(fmaxf(s[i][0], s[i][1]), fmaxf(s[i][2], s[i][3]));
            #pragma unroll
            for (int off = 8; off; off >>= 1)
                mx = fmaxf(mx, __shfl_xor_sync(0xffffffffu, mx, off));
            float mn = fmaxf(mrow[i], mx);
            float alpha = __expf(mrow[i] - mn);
            mrow[i] = mn;
            float rs = 0.f;
            #pragma unroll
            for (int j = 0; j < 4; j++) {
                float p = __expf(s[i][j] - mn);
                s[i][j] = p; rs += p;
            }
            #pragma unroll
            for (int off = 8; off; off >>= 1)
                rs += __shfl_xor_sync(0xffffffffu, rs, off);
            lrow[i] = lrow[i] * alpha + rs;
            #pragma unroll
            for (int j = 0; j < 4; j++) o[i][j] *= alpha;
        }
        __syncthreads();
        #pragma unroll
        for (int i = 0; i < 8; i++)
            #pragma unroll
            for (int j = 0; j < 4; j++)
                KP[(tidx*4 + j) * APAD + tidy*8 + i] = s[i][j];
        __syncthreads();
        #pragma unroll
        for (int kk = 0; kk < 64; kk++) {
            float a[8], bb[4];
            *(float4*)&a[0]  = *(const float4*)(KP + kk * APAD + tidy*8);
            *(float4*)&a[4]  = *(const float4*)(KP + kk * APAD + tidy*8 + 4);
            *(float4*)&bb[0] = *(const float4*)(Vs + kk * APAD + tidx*4);
            #pragma unroll
            for (int i = 0; i < 8; i++)
                #pragma unroll
                for (int j = 0; j < 4; j++)
                    o[i][j] = fmaf(a[i], bb[j], o[i][j]);
        }
    }

    #pragma unroll
    for (int i = 0; i < 8; i++) {
        int q = q0 + tidy*8 + i;
        if (q < SEQ) {
            float inv = 1.f / lrow[i];
            float4 wv = make_float4(o[i][0]*inv, o[i][1]*inv, o[i][2]*inv, o[i][3]*inv);
            *(float4*)(ctx + (size_t)(b * SEQ + q) * EMB + h * DH + tidx*4) = wv;
        }
    }
}

// ---------------- codebook squared norms ----------------
__global__ void sqnorm_kernel(const float* __restrict__ cb, float* __restrict__ out)
{
    int gid  = blockIdx.x * blockDim.x + threadIdx.x;
    int row  = gid >> 5, lane = gid & 31;
    if (row >= CBN) return;
    const float* r = cb + (size_t)row * EMB;
    float s = 0.f;
    for (int c = lane; c < EMB; c += 32) { float v = r[c]; s = fmaf(v, v, s); }
    #pragma unroll
    for (int off = 16; off; off >>= 1) s += __shfl_xor_sync(0xffffffffu, s, off);
    if (lane == 0) out[row] = s;
}

// ---------------- exact fp32 rescore of candidates ----------------
__global__ void __launch_bounds__(256) rescore_kernel(
    const float* __restrict__ fc, const float* __restrict__ cb,
    const float* __restrict__ cbn2, const int* __restrict__ cand,
    float* __restrict__ outTok)
{
    __shared__ float xs[EMB];
    __shared__ float wb[8];
    __shared__ int   wi[8];
    const int row = blockIdx.x;
    const int t = threadIdx.x, lane = t & 31, w = t >> 5;
    ((float2*)xs)[t] = ((const float2*)(fc + (size_t)row * EMB))[t];
    __syncthreads();
    float best = 3.4e38f; int bi = 0x7fffffff;
    #pragma unroll
    for (int k = 0; k < 8; k++) {
        int ci = cand[(size_t)row * NCAND + w * 8 + k];
        const float* c = cb + (size_t)ci * EMB;
        float dot = 0.f;
        #pragma unroll
        for (int e = 0; e < 16; e++)
            dot = fmaf(xs[lane + e*32], __ldg(c + lane + e*32), dot);
        #pragma unroll
        for (int off = 16; off; off >>= 1)
            dot += __shfl_xor_sync(0xffffffffu, dot, off);
        float d = fmaf(-2.f, dot, cbn2[ci]);
        if (d < best || (d == best && ci < bi)) { best = d; bi = ci; }
    }
    if (lane == 0) { wb[w] = best; wi[w] = bi; }
    __syncthreads();
    if (t == 0) {
        float b = wb[0]; int i0 = wi[0];
        #pragma unroll
        for (int j = 1; j < 8; j++)
            if (wb[j] < b || (wb[j] == b && wi[j] < i0)) { b = wb[j]; i0 = wi[j]; }
        outTok[row] = (float)i0;
    }
}

// ---------------- host orchestration ----------------
static inline void run_gemm(int mode, const float* A, const float* W, const float* bias,
                            float* C, int M, int N, int K,
                            const float* resid, const float* sc)
{
    dim3 grid(N / 128, M / 128);
    switch (mode) {
    case 0: gemm_mma<0><<<grid, 256, GEMM_SMEM>>>(A, W, bias, C, M, N, K, resid, sc, nullptr, nullptr); break;
    case 1: gemm_mma<1><<<grid, 256, GEMM_SMEM>>>(A, W, bias, C, M, N, K, resid, sc, nullptr, nullptr); break;
    case 2: gemm_mma<2><<<grid, 256, GEMM_SMEM>>>(A, W, bias, C, M, N, K, resid, sc, nullptr, nullptr); break;
    case 3: gemm_mma<3><<<grid, 256, GEMM_SMEM>>>(A, W, bias, C, M, N, K, resid, sc, nullptr, nullptr); break;
    }
}

extern "C" void kernel_launch(void* const* d_in, const int* in_sizes, int n_in,
                              void* d_out, int out_size)
{
    const int*   tok    = (const int*)  d_in[0];
    const float* cb     = (const float*)d_in[1];
    const float* pe     = (const float*)d_in[2];
    const float* qkv_w  = (const float*)d_in[3];
    const float* qkv_b  = (const float*)d_in[4];
    const float* out_w  = (const float*)d_in[5];
    const float* out_b  = (const float*)d_in[6];
    const float* ln1_g  = (const float*)d_in[7];
    const float* ln1_b  = (const float*)d_in[8];
    const float* ln2_g  = (const float*)d_in[9];
    const float* ln2_b  = (const float*)d_in[10];
    const float* ff1_w  = (const float*)d_in[11];
    const float* ff1_b  = (const float*)d_in[12];
    const float* ff2_w  = (const float*)d_in[13];
    const float* ff2_b  = (const float*)d_in[14];
    const float* fin_g  = (const float*)d_in[15];
    const float* fin_b  = (const float*)d_in[16];
    const float* pp1_w  = (const float*)d_in[17];
    const float* pp1_b  = (const float*)d_in[18];
    const float* ppln_g = (const float*)d_in[19];
    const float* ppln_b = (const float*)d_in[20];
    const float* pp2_w  = (const float*)d_in[21];
    const float* pp2_b  = (const float*)d_in[22];
    const float* res_w  = (const float*)d_in[23];
    const float* fc1_w  = (const float*)d_in[24];
    const float* fc1_b  = (const float*)d_in[25];
    const float* fcln_g = (const float*)d_in[26];
    const float* fcln_b = (const float*)d_in[27];
    const float* fc2_w  = (const float*)d_in[28];
    const float* fc2_b  = (const float*)d_in[29];

    float *x, *y, *h, *qkv, *ctx, *tbuf, *enh, *cbn2; int* pidx;
    cudaGetSymbolAddress((void**)&x,    g_x);
    cudaGetSymbolAddress((void**)&y,    g_y);
    cudaGetSymbolAddress((void**)&h,    g_h);
    cudaGetSymbolAddress((void**)&qkv,  g_qkv);
    cudaGetSymbolAddress((void**)&ctx,  g_ctx);
    cudaGetSymbolAddress((void**)&tbuf, g_t);
    cudaGetSymbolAddress((void**)&enh,  g_enh);
    cudaGetSymbolAddress((void**)&cbn2, g_cbn2);
    cudaGetSymbolAddress((void**)&pidx, g_pidx);

    cudaFuncSetAttribute(attn_kernel, cudaFuncAttributeMaxDynamicSharedMemorySize, ASMEM);
    cudaFuncSetAttribute(gemm_mma<0>, cudaFuncAttributeMaxDynamicSharedMemorySize, GEMM_SMEM);
    cudaFuncSetAttribute(gemm_mma<1>, cudaFuncAttributeMaxDynamicSharedMemorySize, GEMM_SMEM);
    cudaFuncSetAttribute(gemm_mma<2>, cudaFuncAttributeMaxDynamicSharedMemorySize, GEMM_SMEM);
    cudaFuncSetAttribute(gemm_mma<3>, cudaFuncAttributeMaxDynamicSharedMemorySize, GEMM_SMEM);
    cudaFuncSetAttribute(gemm_mma<4>, cudaFuncAttributeMaxDynamicSharedMemorySize, GEMM_SMEM);

    float* fc_out = (float*)d_out;
    const int M = MTOK;

    embed_kernel<<<(M * (EMB/4) + 255) / 256, 256>>>(tok, cb, pe, x, y);

    for (int l = 0; l < NL; l++) {
        ln_kernel<<<M, 128>>>(y, ln1_g + l*EMB, ln1_b + l*EMB, h, 0);
        run_gemm(0, h, qkv_w + (size_t)l*E3*EMB, qkv_b + (size_t)l*E3, qkv, M, E3, EMB, nullptr, nullptr);
        attn_kernel<<<dim3((SEQ+63)/64, NH, BATCH), 128, ASMEM>>>(qkv, ctx);
        run_gemm(2, ctx, out_w + (size_t)l*EMB*EMB, out_b + (size_t)l*EMB, y, M, EMB, EMB, y, nullptr);
        ln_kernel<<<M, 128>>>(y, ln2_g + l*EMB, ln2_b + l*EMB, h, 0);
        run_gemm(1, h, ff1_w + (size_t)l*FF*EMB, ff1_b + (size_t)l*FF, tbuf, M, FF, EMB, nullptr, nullptr);
        run_gemm(2, tbuf, ff2_w + (size_t)l*EMB*FF, ff2_b + (size_t)l*EMB, y, M, EMB, FF, y, nullptr);
    }

    ln_kernel<<<M, 128>>>(y, fin_g, fin_b, h, 0);
    run_gemm(0, h, pp1_w, pp1_b, ctx, M, EMB, EMB, nullptr, nullptr);
    ln_kernel<<<M, 128>>>(ctx, ppln_g, ppln_b, tbuf, 1);
    run_gemm(3, tbuf, pp2_w, pp2_b, enh, M, EMB, EMB, x, res_w);
    run_gemm(0, enh, fc1_w, fc1_b, ctx, M, EMB, EMB, nullptr, nullptr);
    ln_kernel<<<M, 128>>>(ctx, fcln_g, fcln_b, tbuf, 1);
    run_gemm(0, tbuf, fc2_w, fc2_b, fc_out, M, EMB, EMB, nullptr, nullptr);

    if (out_size >= MTOK * EMB + MTOK) {
        sqnorm_kernel<<<(CBN * 32 + 255) / 256, 256>>>(cb, cbn2);
        dim3 grid(CBN / 128, M / 128);
        gemm_mma<4><<<grid, 256, GEMM_SMEM>>>(fc_out, cb, nullptr, nullptr, M, CBN, EMB,
                                              nullptr, nullptr, cbn2, pidx);
        rescore_kernel<<<MTOK, 256>>>(fc_out, cb, cbn2, pidx, fc_out + (size_t)MTOK * EMB);
    }
}

// round 5
// speedup vs baseline: 2.7568x; 1.3210x over previous
#include <cuda_runtime.h>
#include <cuda_bf16.h>
#include <math.h>
#include <stdint.h>

// ---------------- problem constants ----------------
#define BATCH 16
#define SEQ   1000
#define EMB   512
#define NH    8
#define DH    64
#define FF    2048
#define CBN   4096
#define NL    4
#define E3    1536
#define MTOK  (BATCH*SEQ)       // 16000
#define NCAND 64                // quantize candidates per row (2 per 128-col block)

// ---------------- scratch (static device globals; no allocation) ----------------
__device__ __align__(16) static float g_x   [MTOK*EMB];
__device__ __align__(16) static float g_y   [MTOK*EMB];
__device__ __align__(16) static float g_h   [MTOK*EMB];
__device__ __align__(16) static float g_qkv [MTOK*E3];
__device__ __align__(16) static float g_ctx [MTOK*EMB];
__device__ __align__(16) static float g_t   [MTOK*FF];
__device__ __align__(16) static float g_enh [MTOK*EMB];
__device__ __align__(16) static float g_cbn2[CBN];
__device__ __align__(16) static int   g_pidx[MTOK*NCAND];

// ================= helpers =================
__device__ __forceinline__ uint32_t smem_u32(const void* p) {
    uint32_t a;
    asm("{ .reg .u64 t; cvta.to.shared.u64 t, %1; cvt.u32.u64 %0, t; }" : "=r"(a) : "l"(p));
    return a;
}

__device__ __forceinline__ void ldsm4(uint32_t* r, uint32_t addr) {
    asm volatile("ldmatrix.sync.aligned.m8n8.x4.shared.b16 {%0,%1,%2,%3}, [%4];"
                 : "=r"(r[0]), "=r"(r[1]), "=r"(r[2]), "=r"(r[3]) : "r"(addr));
}

__device__ __forceinline__ void ldsm4t(uint32_t* r, uint32_t addr) {
    asm volatile("ldmatrix.sync.aligned.m8n8.x4.trans.shared.b16 {%0,%1,%2,%3}, [%4];"
                 : "=r"(r[0]), "=r"(r[1]), "=r"(r[2]), "=r"(r[3]) : "r"(addr));
}

__device__ __forceinline__ void mma_bf16(float* c, const uint32_t* a, const uint32_t* b) {
    asm volatile("mma.sync.aligned.m16n8k16.row.col.f32.bf16.bf16.f32 "
                 "{%0,%1,%2,%3}, {%4,%5,%6,%7}, {%8,%9}, {%0,%1,%2,%3};"
                 : "+f"(c[0]), "+f"(c[1]), "+f"(c[2]), "+f"(c[3])
                 : "r"(a[0]), "r"(a[1]), "r"(a[2]), "r"(a[3]), "r"(b[0]), "r"(b[1]));
}

__device__ __forceinline__ uint32_t sw128(uint32_t off) {
    return off ^ ((off >> 3) & 0x70);
}

// fp32x4 -> hi/lo bf16x2 pairs
__device__ __forceinline__ void cvt_hilo(float4 v, uint2& hi, uint2& lo) {
    uint32_t h0, h1;
    asm("cvt.rn.bf16x2.f32 %0, %1, %2;" : "=r"(h0) : "f"(v.y), "f"(v.x));
    asm("cvt.rn.bf16x2.f32 %0, %1, %2;" : "=r"(h1) : "f"(v.w), "f"(v.z));
    float hx = __uint_as_float(h0 << 16);
    float hy = __uint_as_float(h0 & 0xffff0000u);
    float hz = __uint_as_float(h1 << 16);
    float hw = __uint_as_float(h1 & 0xffff0000u);
    uint32_t l0, l1;
    asm("cvt.rn.bf16x2.f32 %0, %1, %2;" : "=r"(l0) : "f"(v.y - hy), "f"(v.x - hx));
    asm("cvt.rn.bf16x2.f32 %0, %1, %2;" : "=r"(l1) : "f"(v.w - hw), "f"(v.z - hz));
    hi = make_uint2(h0, h1);
    lo = make_uint2(l0, l1);
}

// store one float4 (4 k-elems) as hi/lo into a 128B-row tile; row layout [hi 64B | lo 64B]
__device__ __forceinline__ void sts_hilo(char* tile, int row, int c4, float4 v) {
    uint2 hi, lo;
    cvt_hilo(v, hi, lo);
    uint32_t off = (uint32_t)(row * 128 + c4 * 8);
    *(uint2*)(tile + sw128(off))      = hi;
    *(uint2*)(tile + sw128(off + 64)) = lo;
}

// ---------------- embed ----------------
__global__ void embed_kernel(const int* __restrict__ tok, const float* __restrict__ cb,
                             const float* __restrict__ pe, float* __restrict__ x,
                             float* __restrict__ y)
{
    int i = blockIdx.x * blockDim.x + threadIdx.x;
    if (i >= MTOK * (EMB/4)) return;
    int row = i >> 7;
    int c4  = i & 127;
    int s   = row % SEQ;
    int tk  = tok[row];
    float4 a = *(const float4*)(cb + (size_t)tk * EMB + c4*4);
    float4 p = *(const float4*)(pe + (size_t)s  * EMB + c4*4);
    float4 v = make_float4(a.x+p.x, a.y+p.y, a.z+p.z, a.w+p.w);
    ((float4*)x)[i] = v;
    ((float4*)y)[i] = v;
}

// ---------------- layernorm ----------------
__global__ void __launch_bounds__(128) ln_kernel(const float* __restrict__ in,
                                                 const float* __restrict__ gam,
                                                 const float* __restrict__ bet,
                                                 float* __restrict__ out, int dogelu)
{
    int row = blockIdx.x;
    int t   = threadIdx.x;
    const float4 v = ((const float4*)(in + (size_t)row * EMB))[t];
    float s  = v.x + v.y + v.z + v.w;
    float ss = v.x*v.x + v.y*v.y + v.z*v.z + v.w*v.w;
    #pragma unroll
    for (int off = 16; off; off >>= 1) {
        s  += __shfl_xor_sync(0xffffffffu, s,  off);
        ss += __shfl_xor_sync(0xffffffffu, ss, off);
    }
    __shared__ float sh[8];
    if ((t & 31) == 0) { sh[t >> 5] = s; sh[4 + (t >> 5)] = ss; }
    __syncthreads();
    s  = sh[0] + sh[1] + sh[2] + sh[3];
    ss = sh[4] + sh[5] + sh[6] + sh[7];
    float mean = s * (1.f / EMB);
    float var  = ss * (1.f / EMB) - mean * mean;
    float rstd = rsqrtf(var + 1e-5f);
    float4 gv = ((const float4*)gam)[t];
    float4 bv = ((const float4*)bet)[t];
    float4 ov;
    ov.x = (v.x - mean) * rstd * gv.x + bv.x;
    ov.y = (v.y - mean) * rstd * gv.y + bv.y;
    ov.z = (v.z - mean) * rstd * gv.z + bv.z;
    ov.w = (v.w - mean) * rstd * gv.w + bv.w;
    if (dogelu) {
        ov.x *= normcdff(ov.x);
        ov.y *= normcdff(ov.y);
        ov.z *= normcdff(ov.z);
        ov.w *= normcdff(ov.w);
    }
    ((float4*)(out + (size_t)row * EMB))[t] = ov;
}

// ================= mma.sync GEMM (unchanged from round 4) =================
#define STAGE_B 32768
#define GEMM_SMEM (2*STAGE_B + 1024)

template<int MODE>
__global__ void __launch_bounds__(256) gemm_mma(
    const float* __restrict__ A, const float* __restrict__ W,
    const float* __restrict__ bias, float* __restrict__ C,
    int M, int N, int K,
    const float* __restrict__ resid, const float* __restrict__ scp,
    const float* __restrict__ cbn2, int* __restrict__ pidx)
{
    extern __shared__ char smraw[];
    uint32_t raw = smem_u32(smraw);
    uint32_t base = (raw + 1023) & ~1023u;
    char* sm0 = smraw + (base - raw);

    const int t    = threadIdx.x;
    const int lane = t & 31;
    const int w    = t >> 5;
    const int wm   = w >> 2;
    const int wn   = w & 3;
    const int m0 = blockIdx.y * 128;
    const int n0 = blockIdx.x * 128;
    const int chunks = K / 32;

    float acc[4][4][4];
    #pragma unroll
    for (int i = 0; i < 4; i++)
        #pragma unroll
        for (int j = 0; j < 4; j++)
            #pragma unroll
            for (int k = 0; k < 4; k++) acc[i][j][k] = 0.f;

    {
        char* dA = sm0;
        char* dB = sm0 + 16384;
        #pragma unroll
        for (int i = 0; i < 4; i++) {
            int idx = i * 256 + t;
            int row = idx >> 3, c4 = idx & 7;
            float4 va = *(const float4*)(A + (size_t)(m0 + row) * K + c4 * 4);
            float4 vb = *(const float4*)(W + (size_t)(n0 + row) * K + c4 * 4);
            sts_hilo(dA, row, c4, va);
            sts_hilo(dB, row, c4, vb);
        }
        __syncthreads();
    }

    const uint32_t aoff0 = (uint32_t)((wm * 64 + (lane & 15)) * 128 + (lane >> 4) * 16);
    const uint32_t boff0 = (uint32_t)((wn * 32 + ((lane >> 4) << 3) + (lane & 7)) * 128
                                      + ((lane >> 3) & 1) * 16);

    for (int c = 0; c < chunks; c++) {
        int buf = c & 1;
        float4 pa[4], pb[4];
        if (c + 1 < chunks) {
            int k0 = (c + 1) * 32;
            #pragma unroll
            for (int i = 0; i < 4; i++) {
                int idx = i * 256 + t;
                int row = idx >> 3, c4 = idx & 7;
                pa[i] = *(const float4*)(A + (size_t)(m0 + row) * K + k0 + c4 * 4);
                pb[i] = *(const float4*)(W + (size_t)(n0 + row) * K + k0 + c4 * 4);
            }
        }

        uint32_t tA = base + buf * STAGE_B;
        uint32_t tB = tA + 16384;
        #pragma unroll
        for (int ks = 0; ks < 2; ks++) {
            uint32_t ah[4][4], al[4][4], bh[4][2], bl[4][2];
            #pragma unroll
            for (int mt = 0; mt < 4; mt++) {
                uint32_t offh = aoff0 + mt * (16 * 128) + ks * 32;
                ldsm4(ah[mt], tA + sw128(offh));
                ldsm4(al[mt], tA + sw128(offh + 64));
            }
            #pragma unroll
            for (int np = 0; np < 2; np++) {
                uint32_t offh = boff0 + np * (16 * 128) + ks * 32;
                uint32_t r[4];
                ldsm4(r, tB + sw128(offh));
                bh[np*2][0] = r[0]; bh[np*2][1] = r[1];
                bh[np*2+1][0] = r[2]; bh[np*2+1][1] = r[3];
                ldsm4(r, tB + sw128(offh + 64));
                bl[np*2][0] = r[0]; bl[np*2][1] = r[1];
                bl[np*2+1][0] = r[2]; bl[np*2+1][1] = r[3];
            }
            #pragma unroll
            for (int mt = 0; mt < 4; mt++)
                #pragma unroll
                for (int nt = 0; nt < 4; nt++) {
                    mma_bf16(acc[mt][nt], ah[mt], bh[nt]);
                    mma_bf16(acc[mt][nt], ah[mt], bl[nt]);
                    mma_bf16(acc[mt][nt], al[mt], bh[nt]);
                }
        }
        __syncthreads();
        if (c + 1 < chunks) {
            char* dA = sm0 + (buf ^ 1) * STAGE_B;
            char* dB = dA + 16384;
            #pragma unroll
            for (int i = 0; i < 4; i++) {
                int idx = i * 256 + t;
                int row = idx >> 3, c4 = idx & 7;
                sts_hilo(dA, row, c4, pa[i]);
                sts_hilo(dB, row, c4, pb[i]);
            }
            __syncthreads();
        }
    }

    if (MODE == 4) {
        float* psm = (float*)sm0;
        int*   pim = (int*)(sm0 + 128*4*2*4);
        #pragma unroll
        for (int mt = 0; mt < 4; mt++) {
            float b0[2] = {3.4e38f, 3.4e38f}, b1[2] = {3.4e38f, 3.4e38f};
            int   i0v[2] = {0x7fffffff, 0x7fffffff}, i1v[2] = {0x7fffffff, 0x7fffffff};
            #pragma unroll
            for (int nt = 0; nt < 4; nt++) {
                int n = n0 + wn * 32 + nt * 8 + (lane & 3) * 2;
                float c0 = cbn2[n], c1 = cbn2[n + 1];
                float dv[2][2];
                dv[0][0] = fmaf(-2.f, acc[mt][nt][0], c0);
                dv[0][1] = fmaf(-2.f, acc[mt][nt][1], c1);
                dv[1][0] = fmaf(-2.f, acc[mt][nt][2], c0);
                dv[1][1] = fmaf(-2.f, acc[mt][nt][3], c1);
                #pragma unroll
                for (int rr = 0; rr < 2; rr++)
                    #pragma unroll
                    for (int jj = 0; jj < 2; jj++) {
                        float d = dv[rr][jj]; int nn = n + jj;
                        if (d < b0[rr] || (d == b0[rr] && nn < i0v[rr])) {
                            b1[rr] = b0[rr]; i1v[rr] = i0v[rr];
                            b0[rr] = d; i0v[rr] = nn;
                        } else if (d < b1[rr] || (d == b1[rr] && nn < i1v[rr])) {
                            b1[rr] = d; i1v[rr] = nn;
                        }
                    }
            }
            #pragma unroll
            for (int off = 1; off < 4; off <<= 1) {
                #pragma unroll
                for (int rr = 0; rr < 2; rr++) {
                    float o0 = __shfl_xor_sync(0xffffffffu, b0[rr], off);
                    int   q0 = __shfl_xor_sync(0xffffffffu, i0v[rr], off);
                    float o1 = __shfl_xor_sync(0xffffffffu, b1[rr], off);
                    int   q1 = __shfl_xor_sync(0xffffffffu, i1v[rr], off);
                    if (o0 < b0[rr] || (o0 == b0[rr] && q0 < i0v[rr])) {
                        b1[rr] = b0[rr]; i1v[rr] = i0v[rr];
                        b0[rr] = o0; i0v[rr] = q0;
                    } else if (o0 < b1[rr] || (o0 == b1[rr] && q0 < i1v[rr])) {
                        b1[rr] = o0; i1v[rr] = q0;
                    }
                    if (o1 < b1[rr] || (o1 == b1[rr] && q1 < i1v[rr])) {
                        b1[rr] = o1; i1v[rr] = q1;
                    }
                }
            }
            if ((lane & 3) == 0) {
                int rl = wm * 64 + mt * 16 + (lane >> 2);
                psm[(rl*4 + wn)*2 + 0]     = b0[0]; pim[(rl*4 + wn)*2 + 0]     = i0v[0];
                psm[(rl*4 + wn)*2 + 1]     = b1[0]; pim[(rl*4 + wn)*2 + 1]     = i1v[0];
                psm[((rl+8)*4 + wn)*2 + 0] = b0[1]; pim[((rl+8)*4 + wn)*2 + 0] = i0v[1];
                psm[((rl+8)*4 + wn)*2 + 1] = b1[1]; pim[((rl+8)*4 + wn)*2 + 1] = i1v[1];
            }
        }
        __syncthreads();
        if (t < 128) {
            float b0 = 3.4e38f, b1 = 3.4e38f;
            int i0 = 0x7fffffff, i1 = 0x7fffffff;
            #pragma unroll
            for (int j = 0; j < 8; j++) {
                float v = psm[t*8 + j]; int id = pim[t*8 + j];
                if (v < b0 || (v == b0 && id < i0)) {
                    b1 = b0; i1 = i0; b0 = v; i0 = id;
                } else if (v < b1 || (v == b1 && id < i1)) {
                    b1 = v; i1 = id;
                }
            }
            size_t o = (size_t)(m0 + t) * NCAND + blockIdx.x * 2;
            pidx[o]     = i0;
            pidx[o + 1] = i1;
        }
        return;
    }

    const float scv = (MODE == 3) ? *scp : 1.f;
    #pragma unroll
    for (int mt = 0; mt < 4; mt++) {
        int rb = m0 + wm * 64 + mt * 16 + (lane >> 2);
        #pragma unroll
        for (int nt = 0; nt < 4; nt++) {
            int col = n0 + wn * 32 + nt * 8 + (lane & 3) * 2;
            float b0 = bias[col], b1 = bias[col + 1];
            float v0 = acc[mt][nt][0] + b0;
            float v1 = acc[mt][nt][1] + b1;
            float v2 = acc[mt][nt][2] + b0;
            float v3 = acc[mt][nt][3] + b1;
            size_t o0 = (size_t)rb * N + col;
            size_t o1 = (size_t)(rb + 8) * N + col;
            if (MODE == 1) {
                v0 *= normcdff(v0); v1 *= normcdff(v1);
                v2 *= normcdff(v2); v3 *= normcdff(v3);
            }
            if (MODE == 2) {
                v0 += resid[o0]; v1 += resid[o0 + 1];
                v2 += resid[o1]; v3 += resid[o1 + 1];
            }
            if (MODE == 3) {
                v0 = resid[o0] + scv * v0; v1 = resid[o0 + 1] + scv * v1;
                v2 = resid[o1] + scv * v2; v3 = resid[o1 + 1] + scv * v3;
            }
            *(float2*)(C + o0) = make_float2(v0, v1);
            *(float2*)(C + o1) = make_float2(v2, v3);
        }
    }
}

// ================= tensor-core flash attention =================
// CTA: 256 threads (8 warps), q-tile 128, k-tile 128, dh=64.
// S-phase warp grid 2x4 (warp tile 64x32); PV-phase warp grid 8x1 (16 q-rows x 64 dh).
// All operands bf16 hi/lo (3-mma split) with fp32 accumulate.
#define NKT 8
#define AQ_OFF   0          // 32 KB: 2 chunks (dh 32-groups) x 128 rows x 128B
#define AK_OFF   32768      // 32 KB
#define AV_OFF   65536      // 32 KB (rows = k, consumed via ldmatrix.trans)
#define AP_OFF   98304      // 64 KB: 4 chunks (k 32-groups) x 128 rows x 128B
#define ARED_OFF 163840     // float[128][4]
#define AMS_OFF  165888     // float[128]
#define ALS_OFF  166400
#define AAS_OFF  166912
#define ATT_SMEM 168448

__global__ void __launch_bounds__(256, 1) attn_mma(const float* __restrict__ qkv,
                                                   float* __restrict__ ctx)
{
    extern __shared__ char smraw[];
    uint32_t raw = smem_u32(smraw);
    uint32_t base = (raw + 1023) & ~1023u;
    char* sm0 = smraw + (base - raw);

    const int t    = threadIdx.x;
    const int lane = t & 31;
    const int w    = t >> 5;
    const int wm   = w >> 2, wn = w & 3;
    const int q0 = blockIdx.x * 128;
    const int h  = blockIdx.y, b = blockIdx.z;
    const float* gq = qkv + (size_t)b * SEQ * E3 + h * DH;

    float* red = (float*)(sm0 + ARED_OFF);
    float* m_s = (float*)(sm0 + AMS_OFF);
    float* l_s = (float*)(sm0 + ALS_OFF);
    float* a_s = (float*)(sm0 + AAS_OFF);

    // stage Q (scaled by 1/sqrt(DH)=0.125)
    #pragma unroll
    for (int ch = 0; ch < 2; ch++) {
        char* dst = sm0 + AQ_OFF + ch * 16384;
        #pragma unroll
        for (int i = 0; i < 4; i++) {
            int idx = i * 256 + t;
            int row = idx >> 3, c4 = idx & 7;
            float4 v = make_float4(0.f, 0.f, 0.f, 0.f);
            if (q0 + row < SEQ)
                v = *(const float4*)(gq + (size_t)(q0 + row) * E3 + ch*32 + c4*4);
            v.x *= 0.125f; v.y *= 0.125f; v.z *= 0.125f; v.w *= 0.125f;
            sts_hilo(dst, row, c4, v);
        }
    }
    if (t < 128) { m_s[t] = -1e30f; l_s[t] = 0.f; }

    // stage K/V tile 0
    #pragma unroll
    for (int ch = 0; ch < 2; ch++) {
        #pragma unroll
        for (int i = 0; i < 4; i++) {
            int idx = i * 256 + t;
            int row = idx >> 3, c4 = idx & 7;
            float4 kv = make_float4(0,0,0,0), vv = make_float4(0,0,0,0);
            if (row < SEQ) {
                const float* p = gq + (size_t)row * E3 + ch*32 + c4*4;
                kv = *(const float4*)(p + EMB);
                vv = *(const float4*)(p + 2*EMB);
            }
            sts_hilo(sm0 + AK_OFF + ch*16384, row, c4, kv);
            sts_hilo(sm0 + AV_OFF + ch*16384, row, c4, vv);
        }
    }
    __syncthreads();

    float acc_o[8][4];
    #pragma unroll
    for (int i = 0; i < 8; i++)
        #pragma unroll
        for (int j = 0; j < 4; j++) acc_o[i][j] = 0.f;

    const uint32_t aoff0 = (uint32_t)((wm*64 + (lane & 15)) * 128 + ((lane >> 4) << 4));
    const uint32_t boff0 = (uint32_t)((wn*32 + ((lane >> 4) << 3) + (lane & 7)) * 128
                                      + (((lane >> 3) & 1) << 4));
    const uint32_t poff0 = (uint32_t)((w*16 + (lane & 15)) * 128 + ((lane >> 4) << 4));
    const uint32_t voff0 = (uint32_t)((lane & 15) * 128 + ((lane >> 4) << 4));

    for (int kt = 0; kt < NKT; kt++) {
        // ---- S = Q @ K^T ----
        float acc[4][4][4];
        #pragma unroll
        for (int i = 0; i < 4; i++)
            #pragma unroll
            for (int j = 0; j < 4; j++)
                #pragma unroll
                for (int k = 0; k < 4; k++) acc[i][j][k] = 0.f;

        uint32_t tQ = base + AQ_OFF, tK = base + AK_OFF;
        #pragma unroll
        for (int ch = 0; ch < 2; ch++) {
            #pragma unroll
            for (int ks = 0; ks < 2; ks++) {
                uint32_t ah[4][4], al[4][4], bh[4][2], bl[4][2];
                #pragma unroll
                for (int mt = 0; mt < 4; mt++) {
                    uint32_t offh = aoff0 + mt * 2048 + ks * 32;
                    ldsm4(ah[mt], tQ + ch*16384 + sw128(offh));
                    ldsm4(al[mt], tQ + ch*16384 + sw128(offh + 64));
                }
                #pragma unroll
                for (int np = 0; np < 2; np++) {
                    uint32_t offh = boff0 + np * 2048 + ks * 32;
                    uint32_t r[4];
                    ldsm4(r, tK + ch*16384 + sw128(offh));
                    bh[np*2][0] = r[0]; bh[np*2][1] = r[1];
                    bh[np*2+1][0] = r[2]; bh[np*2+1][1] = r[3];
                    ldsm4(r, tK + ch*16384 + sw128(offh + 64));
                    bl[np*2][0] = r[0]; bl[np*2][1] = r[1];
                    bl[np*2+1][0] = r[2]; bl[np*2+1][1] = r[3];
                }
                #pragma unroll
                for (int mt = 0; mt < 4; mt++)
                    #pragma unroll
                    for (int nt = 0; nt < 4; nt++) {
                        mma_bf16(acc[mt][nt], ah[mt], bh[nt]);
                        mma_bf16(acc[mt][nt], ah[mt], bl[nt]);
                        mma_bf16(acc[mt][nt], al[mt], bh[nt]);
                    }
            }
        }

        // ---- mask (last k-tile) ----
        if (kt == NKT - 1) {
            #pragma unroll
            for (int nt = 0; nt < 4; nt++)
                #pragma unroll
                for (int j = 0; j < 2; j++) {
                    int col = kt*128 + wn*32 + nt*8 + (lane & 3)*2 + j;
                    if (col >= SEQ) {
                        #pragma unroll
                        for (int mt = 0; mt < 4; mt++) {
                            acc[mt][nt][j]     = -1e30f;
                            acc[mt][nt][2 + j] = -1e30f;
                        }
                    }
                }
        }

        // ---- per-warp row max -> smem ----
        #pragma unroll
        for (int mt = 0; mt < 4; mt++)
            #pragma unroll
            for (int h2 = 0; h2 < 2; h2++) {
                float mx = -1e30f;
                #pragma unroll
                for (int nt = 0; nt < 4; nt++)
                    mx = fmaxf(mx, fmaxf(acc[mt][nt][h2*2], acc[mt][nt][h2*2+1]));
                mx = fmaxf(mx, __shfl_xor_sync(0xffffffffu, mx, 1));
                mx = fmaxf(mx, __shfl_xor_sync(0xffffffffu, mx, 2));
                if ((lane & 3) == 0)
                    red[(wm*64 + mt*16 + (lane >> 2) + h2*8)*4 + wn] = mx;
            }
        __syncthreads();
        if (t < 128) {
            float mx = fmaxf(fmaxf(red[t*4], red[t*4+1]), fmaxf(red[t*4+2], red[t*4+3]));
            float mn = fmaxf(m_s[t], mx);
            a_s[t] = __expf(m_s[t] - mn);
            m_s[t] = mn;
        }
        __syncthreads();

        // ---- exp, row sums, stage P (chunk = wn), rescale O ----
        char* smP = sm0 + AP_OFF + wn * 16384;
        #pragma unroll
        for (int mt = 0; mt < 4; mt++)
            #pragma unroll
            for (int h2 = 0; h2 < 2; h2++) {
                int r = wm*64 + mt*16 + (lane >> 2) + h2*8;
                float mrow = m_s[r];
                float rowsum = 0.f;
                #pragma unroll
                for (int nt = 0; nt < 4; nt++) {
                    float p0 = __expf(acc[mt][nt][h2*2]   - mrow);
                    float p1 = __expf(acc[mt][nt][h2*2+1] - mrow);
                    rowsum += p0 + p1;
                    uint32_t hi;
                    asm("cvt.rn.bf16x2.f32 %0, %1, %2;" : "=r"(hi) : "f"(p1), "f"(p0));
                    float hx = __uint_as_float(hi << 16);
                    float hy = __uint_as_float(hi & 0xffff0000u);
                    uint32_t lo;
                    asm("cvt.rn.bf16x2.f32 %0, %1, %2;" : "=r"(lo) : "f"(p1 - hy), "f"(p0 - hx));
                    uint32_t off = (uint32_t)(r*128 + (nt*8 + (lane & 3)*2)*2);
                    *(uint32_t*)(smP + sw128(off))      = hi;
                    *(uint32_t*)(smP + sw128(off + 64)) = lo;
                }
                rowsum += __shfl_xor_sync(0xffffffffu, rowsum, 1);
                rowsum += __shfl_xor_sync(0xffffffffu, rowsum, 2);
                if ((lane & 3) == 0) red[r*4 + wn] = rowsum;
            }
        // rescale O (PV layout rows)
        {
            int r1 = w*16 + (lane >> 2);
            float al1 = a_s[r1], al2 = a_s[r1 + 8];
            #pragma unroll
            for (int nt = 0; nt < 8; nt++) {
                acc_o[nt][0] *= al1; acc_o[nt][1] *= al1;
                acc_o[nt][2] *= al2; acc_o[nt][3] *= al2;
            }
        }
        __syncthreads();
        if (t < 128)
            l_s[t] = l_s[t] * a_s[t] + red[t*4] + red[t*4+1] + red[t*4+2] + red[t*4+3];

        // ---- O += P @ V ----
        uint32_t tP = base + AP_OFF, tV = base + AV_OFF;
        #pragma unroll
        for (int ks = 0; ks < 8; ks++) {
            uint32_t ap[4], alp[4];
            uint32_t poff = poff0 + (ks & 1) * 32;
            ldsm4(ap,  tP + (ks >> 1)*16384 + sw128(poff));
            ldsm4(alp, tP + (ks >> 1)*16384 + sw128(poff + 64));
            #pragma unroll
            for (int np = 0; np < 4; np++) {
                uint32_t voff = voff0 + ks*2048 + (np & 1)*32;
                uint32_t vbase = tV + (np >> 1)*16384;
                uint32_t rh[4], rl[4];
                ldsm4t(rh, vbase + sw128(voff));
                ldsm4t(rl, vbase + sw128(voff + 64));
                uint32_t bh0[2] = {rh[0], rh[1]}, bh1[2] = {rh[2], rh[3]};
                uint32_t bl0[2] = {rl[0], rl[1]}, bl1[2] = {rl[2], rl[3]};
                mma_bf16(acc_o[np*2],   ap,  bh0);
                mma_bf16(acc_o[np*2],   alp, bh0);
                mma_bf16(acc_o[np*2],   ap,  bl0);
                mma_bf16(acc_o[np*2+1], ap,  bh1);
                mma_bf16(acc_o[np*2+1], alp, bh1);
                mma_bf16(acc_o[np*2+1], ap,  bl1);
            }
        }
        __syncthreads();

        // ---- stage next K/V tile ----
        if (kt + 1 < NKT) {
            #pragma unroll
            for (int ch = 0; ch < 2; ch++) {
                #pragma unroll
                for (int i = 0; i < 4; i++) {
                    int idx = i * 256 + t;
                    int row = idx >> 3, c4 = idx & 7;
                    int krow = (kt + 1)*128 + row;
                    float4 kv = make_float4(0,0,0,0), vv = make_float4(0,0,0,0);
                    if (krow < SEQ) {
                        const float* p = gq + (size_t)krow * E3 + ch*32 + c4*4;
                        kv = *(const float4*)(p + EMB);
                        vv = *(const float4*)(p + 2*EMB);
                    }
                    sts_hilo(sm0 + AK_OFF + ch*16384, row, c4, kv);
                    sts_hilo(sm0 + AV_OFF + ch*16384, row, c4, vv);
                }
            }
            __syncthreads();
        }
    }

    // ---- normalize & store ----
    {
        int r1 = w*16 + (lane >> 2);
        float linv1 = 1.f / l_s[r1];
        float linv2 = 1.f / l_s[r1 + 8];
        int q1 = q0 + r1, q2 = q1 + 8;
        #pragma unroll
        for (int nt = 0; nt < 8; nt++) {
            int col = nt*8 + (lane & 3)*2;
            if (q1 < SEQ)
                *(float2*)(ctx + (size_t)(b * SEQ + q1) * EMB + h*DH + col) =
                    make_float2(acc_o[nt][0]*linv1, acc_o[nt][1]*linv1);
            if (q2 < SEQ)
                *(float2*)(ctx + (size_t)(b * SEQ + q2) * EMB + h*DH + col) =
                    make_float2(acc_o[nt][2]*linv2, acc_o[nt][3]*linv2);
        }
    }
}

// ---------------- codebook squared norms ----------------
__global__ void sqnorm_kernel(const float* __restrict__ cb, float* __restrict__ out)
{
    int gid  = blockIdx.x * blockDim.x + threadIdx.x;
    int row  = gid >> 5, lane = gid & 31;
    if (row >= CBN) return;
    const float* r = cb + (size_t)row * EMB;
    float s = 0.f;
    for (int c = lane; c < EMB; c += 32) { float v = r[c]; s = fmaf(v, v, s); }
    #pragma unroll
    for (int off = 16; off; off >>= 1) s += __shfl_xor_sync(0xffffffffu, s, off);
    if (lane == 0) out[row] = s;
}

// ---------------- exact fp32 rescore of candidates ----------------
__global__ void __launch_bounds__(256) rescore_kernel(
    const float* __restrict__ fc, const float* __restrict__ cb,
    const float* __restrict__ cbn2, const int* __restrict__ cand,
    float* __restrict__ outTok)
{
    __shared__ float xs[EMB];
    __shared__ float wb[8];
    __shared__ int   wi[8];
    const int row = blockIdx.x;
    const int t = threadIdx.x, lane = t & 31, w = t >> 5;
    ((float2*)xs)[t] = ((const float2*)(fc + (size_t)row * EMB))[t];
    __syncthreads();
    float best = 3.4e38f; int bi = 0x7fffffff;
    #pragma unroll
    for (int k = 0; k < 8; k++) {
        int ci = cand[(size_t)row * NCAND + w * 8 + k];
        const float* c = cb + (size_t)ci * EMB;
        float dot = 0.f;
        #pragma unroll
        for (int e = 0; e < 16; e++)
            dot = fmaf(xs[lane + e*32], __ldg(c + lane + e*32), dot);
        #pragma unroll
        for (int off = 16; off; off >>= 1)
            dot += __shfl_xor_sync(0xffffffffu, dot, off);
        float d = fmaf(-2.f, dot, cbn2[ci]);
        if (d < best || (d == best && ci < bi)) { best = d; bi = ci; }
    }
    if (lane == 0) { wb[w] = best; wi[w] = bi; }
    __syncthreads();
    if (t == 0) {
        float b = wb[0]; int i0 = wi[0];
        #pragma unroll
        for (int j = 1; j < 8; j++)
            if (wb[j] < b || (wb[j] == b && wi[j] < i0)) { b = wb[j]; i0 = wi[j]; }
        outTok[row] = (float)i0;
    }
}

// ---------------- host orchestration ----------------
static inline void run_gemm(int mode, const float* A, const float* W, const float* bias,
                            float* C, int M, int N, int K,
                            const float* resid, const float* sc)
{
    dim3 grid(N / 128, M / 128);
    switch (mode) {
    case 0: gemm_mma<0><<<grid, 256, GEMM_SMEM>>>(A, W, bias, C, M, N, K, resid, sc, nullptr, nullptr); break;
    case 1: gemm_mma<1><<<grid, 256, GEMM_SMEM>>>(A, W, bias, C, M, N, K, resid, sc, nullptr, nullptr); break;
    case 2: gemm_mma<2><<<grid, 256, GEMM_SMEM>>>(A, W, bias, C, M, N, K, resid, sc, nullptr, nullptr); break;
    case 3: gemm_mma<3><<<grid, 256, GEMM_SMEM>>>(A, W, bias, C, M, N, K, resid, sc, nullptr, nullptr); break;
    }
}

extern "C" void kernel_launch(void* const* d_in, const int* in_sizes, int n_in,
                              void* d_out, int out_size)
{
    const int*   tok    = (const int*)  d_in[0];
    const float* cb     = (const float*)d_in[1];
    const float* pe     = (const float*)d_in[2];
    const float* qkv_w  = (const float*)d_in[3];
    const float* qkv_b  = (const float*)d_in[4];
    const float* out_w  = (const float*)d_in[5];
    const float* out_b  = (const float*)d_in[6];
    const float* ln1_g  = (const float*)d_in[7];
    const float* ln1_b  = (const float*)d_in[8];
    const float* ln2_g  = (const float*)d_in[9];
    const float* ln2_b  = (const float*)d_in[10];
    const float* ff1_w  = (const float*)d_in[11];
    const float* ff1_b  = (const float*)d_in[12];
    const float* ff2_w  = (const float*)d_in[13];
    const float* ff2_b  = (const float*)d_in[14];
    const float* fin_g  = (const float*)d_in[15];
    const float* fin_b  = (const float*)d_in[16];
    const float* pp1_w  = (const float*)d_in[17];
    const float* pp1_b  = (const float*)d_in[18];
    const float* ppln_g = (const float*)d_in[19];
    const float* ppln_b = (const float*)d_in[20];
    const float* pp2_w  = (const float*)d_in[21];
    const float* pp2_b  = (const float*)d_in[22];
    const float* res_w  = (const float*)d_in[23];
    const float* fc1_w  = (const float*)d_in[24];
    const float* fc1_b  = (const float*)d_in[25];
    const float* fcln_g = (const float*)d_in[26];
    const float* fcln_b = (const float*)d_in[27];
    const float* fc2_w  = (const float*)d_in[28];
    const float* fc2_b  = (const float*)d_in[29];

    float *x, *y, *h, *qkv, *ctx, *tbuf, *enh, *cbn2; int* pidx;
    cudaGetSymbolAddress((void**)&x,    g_x);
    cudaGetSymbolAddress((void**)&y,    g_y);
    cudaGetSymbolAddress((void**)&h,    g_h);
    cudaGetSymbolAddress((void**)&qkv,  g_qkv);
    cudaGetSymbolAddress((void**)&ctx,  g_ctx);
    cudaGetSymbolAddress((void**)&tbuf, g_t);
    cudaGetSymbolAddress((void**)&enh,  g_enh);
    cudaGetSymbolAddress((void**)&cbn2, g_cbn2);
    cudaGetSymbolAddress((void**)&pidx, g_pidx);

    cudaFuncSetAttribute(attn_mma, cudaFuncAttributeMaxDynamicSharedMemorySize, ATT_SMEM);
    cudaFuncSetAttribute(gemm_mma<0>, cudaFuncAttributeMaxDynamicSharedMemorySize, GEMM_SMEM);
    cudaFuncSetAttribute(gemm_mma<1>, cudaFuncAttributeMaxDynamicSharedMemorySize, GEMM_SMEM);
    cudaFuncSetAttribute(gemm_mma<2>, cudaFuncAttributeMaxDynamicSharedMemorySize, GEMM_SMEM);
    cudaFuncSetAttribute(gemm_mma<3>, cudaFuncAttributeMaxDynamicSharedMemorySize, GEMM_SMEM);
    cudaFuncSetAttribute(gemm_mma<4>, cudaFuncAttributeMaxDynamicSharedMemorySize, GEMM_SMEM);

    float* fc_out = (float*)d_out;
    const int M = MTOK;

    embed_kernel<<<(M * (EMB/4) + 255) / 256, 256>>>(tok, cb, pe, x, y);

    for (int l = 0; l < NL; l++) {
        ln_kernel<<<M, 128>>>(y, ln1_g + l*EMB, ln1_b + l*EMB, h, 0);
        run_gemm(0, h, qkv_w + (size_t)l*E3*EMB, qkv_b + (size_t)l*E3, qkv, M, E3, EMB, nullptr, nullptr);
        attn_mma<<<dim3((SEQ+127)/128, NH, BATCH), 256, ATT_SMEM>>>(qkv, ctx);
        run_gemm(2, ctx, out_w + (size_t)l*EMB*EMB, out_b + (size_t)l*EMB, y, M, EMB, EMB, y, nullptr);
        ln_kernel<<<M, 128>>>(y, ln2_g + l*EMB, ln2_b + l*EMB, h, 0);
        run_gemm(1, h, ff1_w + (size_t)l*FF*EMB, ff1_b + (size_t)l*FF, tbuf, M, FF, EMB, nullptr, nullptr);
        run_gemm(2, tbuf, ff2_w + (size_t)l*EMB*FF, ff2_b + (size_t)l*EMB, y, M, EMB, FF, y, nullptr);
    }

    ln_kernel<<<M, 128>>>(y, fin_g, fin_b, h, 0);
    run_gemm(0, h, pp1_w, pp1_b, ctx, M, EMB, EMB, nullptr, nullptr);
    ln_kernel<<<M, 128>>>(ctx, ppln_g, ppln_b, tbuf, 1);
    run_gemm(3, tbuf, pp2_w, pp2_b, enh, M, EMB, EMB, x, res_w);
    run_gemm(0, enh, fc1_w, fc1_b, ctx, M, EMB, EMB, nullptr, nullptr);
    ln_kernel<<<M, 128>>>(ctx, fcln_g, fcln_b, tbuf, 1);
    run_gemm(0, tbuf, fc2_w, fc2_b, fc_out, M, EMB, EMB, nullptr, nullptr);

    if (out_size >= MTOK * EMB + MTOK) {
        sqnorm_kernel<<<(CBN * 32 + 255) / 256, 256>>>(cb, cbn2);
        dim3 grid(CBN / 128, M / 128);
        gemm_mma<4><<<grid, 256, GEMM_SMEM>>>(fc_out, cb, nullptr, nullptr, M, CBN, EMB,
                                              nullptr, nullptr, cbn2, pidx);
        rescore_kernel<<<MTOK, 256>>>(fc_out, cb, cbn2, pidx, fc_out + (size_t)MTOK * EMB);
    }
}